// round 10
// baseline (speedup 1.0000x reference)
#include <cuda_runtime.h>
#include <cuda_bf16.h>
#include <cstdint>
#include <math.h>

// Problem constants
#define BB    2
#define LL    2048
#define DIMM  512
#define DINN  1024
#define DSTT  16
#define DTRR  32
#define CK    4
#define ROWS  4096   // B*L
#define NC    16     // scan chunks
#define CL    (LL/NC)

static_assert(CL * NC == LL, "chunking");

// ---------------- scratch (static device globals; no allocation) ----------------
__device__ float  g_u  [ROWS*DINN];
__device__ float  g_g  [ROWS*DINN];
__device__ float  g_bc [2*ROWS*2*DSTT];
__device__ float  g_dl [2*ROWS*DINN];      // delta (fp32)
__device__ float  g_out[ROWS*DIMM];
__device__ float4 g_ch [2*BB*NC*DINN*8];   // per-chunk (h0, p0, h1, p1)
__device__ float2 g_hin[2*BB*NC*DINN*8];   // per-chunk incoming state

// tf32-rounded fp32 GEMM inputs (activations & weights)
__device__ __align__(16) float a_xn[ROWS*DIMM];
__device__ __align__(16) float a_uc[2*ROWS*DINN];
__device__ __align__(16) float a_yc[ROWS*DINN];     // y_f, then (y_f+y_b)*g tf32
__device__ __align__(16) float a_dt[2*ROWS*DTRR];
__device__ __align__(16) float w_in[2048*512];
__device__ __align__(16) float w_op[512*1024];
__device__ __align__(16) float w_xp[2*64*1024];
__device__ __align__(16) float w_dt[2*1024*32];

// ---------------- math helpers ----------------
__device__ __forceinline__ float ex2f_(float x) {
    float r; asm("ex2.approx.ftz.f32 %0, %1;" : "=f"(r) : "f"(x)); return r;
}
__device__ __forceinline__ float siluf_(float v) {
    return __fdividef(v, 1.0f + __expf(-v));
}
__device__ __forceinline__ float softplusf_(float x) {
    return (x > 20.0f) ? x : log1pf(__expf(x));
}
__device__ __forceinline__ float tf32r_(float x) {
    float r; asm("cvt.rna.tf32.f32 %0, %1;" : "=f"(r) : "f"(x)); return r;
}
__device__ __forceinline__ uint32_t smem_u32_(const void* p) {
    uint32_t a;
    asm("{ .reg .u64 t; cvta.to.shared.u64 t, %1; cvt.u32.u64 %0, t; }" : "=r"(a) : "l"(p));
    return a;
}
__device__ __forceinline__ unsigned long long gaddr_(const void* p) {
    return (unsigned long long)__cvta_generic_to_global(p);
}

// mma m16n8k8 row.col tf32 -> f32 (inputs already tf32-rounded)
__device__ __forceinline__ void mma_tf32_(float* c, const uint32_t* a, const uint32_t* b) {
    asm volatile(
        "mma.sync.aligned.m16n8k8.row.col.f32.tf32.tf32.f32 "
        "{%0,%1,%2,%3}, {%4,%5,%6,%7}, {%8,%9}, {%0,%1,%2,%3};"
        : "+f"(c[0]), "+f"(c[1]), "+f"(c[2]), "+f"(c[3])
        : "r"(a[0]), "r"(a[1]), "r"(a[2]), "r"(a[3]), "r"(b[0]), "r"(b[1]));
}

#define CPA16(d, s) asm volatile("cp.async.cg.shared.global [%0], [%1], 16;" :: "r"(d), "l"(s))
#define CPCOMMIT()  asm volatile("cp.async.commit_group;")
template<int N> __device__ __forceinline__ void cpwait_() {
    asm volatile("cp.async.wait_group %0;" :: "n"(N));
}

// ---------------- weight tf32-round (single kernel) ----------------
#define TSEG0 (2048*512)
#define TSEG1 (TSEG0 + 512*1024)
#define TSEG2 (TSEG1 + 64*1024)
#define TSEG3 (TSEG2 + 64*1024)
#define TSEG4 (TSEG3 + 1024*32)
#define TSEG5 (TSEG4 + 1024*32)
__global__ void __launch_bounds__(256) wconv_kernel(
    const float* __restrict__ w_in_s, const float* __restrict__ w_op_s,
    const float* __restrict__ xf,     const float* __restrict__ xb,
    const float* __restrict__ df,     const float* __restrict__ db)
{
    const int i = blockIdx.x*256 + threadIdx.x;
    float v; float* dst; int j;
    if (i < TSEG0)      { j = i;         v = w_in_s[j]; dst = w_in; }
    else if (i < TSEG1) { j = i - TSEG0; v = w_op_s[j]; dst = w_op; }
    else if (i < TSEG2) { j = i - TSEG1; v = xf[j];     dst = w_xp; }
    else if (i < TSEG3) { j = i - TSEG2; v = xb[j];     dst = w_xp + 64*1024; }
    else if (i < TSEG4) { j = i - TSEG3; v = df[j];     dst = w_dt; }
    else                { j = i - TSEG4; v = db[j];     dst = w_dt + 1024*32; }
    dst[j] = tf32r_(v);
}

// ---------------- LayerNorm ----------------
// MODE 0: x -> a_xn (tf32-rounded fp32).  MODE 1: g_out -> out (fp32).
template<int MODE>
__global__ void __launch_bounds__(128) ln_kernel(
    const float* __restrict__ in_arg, const float* __restrict__ w,
    const float* __restrict__ b, float* __restrict__ out_arg)
{
    const float* in = (MODE == 0) ? in_arg : g_out;
    const int row = blockIdx.x;
    const int tid = threadIdx.x;

    const float4 v = *(const float4*)&in[(size_t)row*DIMM + tid*4];
    float s = v.x + v.y + v.z + v.w;
    float q = v.x*v.x + v.y*v.y + v.z*v.z + v.w*v.w;
#pragma unroll
    for (int o = 16; o > 0; o >>= 1) {
        s += __shfl_xor_sync(0xffffffffu, s, o);
        q += __shfl_xor_sync(0xffffffffu, q, o);
    }
    __shared__ float ss[4], qs[4];
    const int wid = tid >> 5;
    if ((tid & 31) == 0) { ss[wid] = s; qs[wid] = q; }
    __syncthreads();
    const float S = ss[0] + ss[1] + ss[2] + ss[3];
    const float Q = qs[0] + qs[1] + qs[2] + qs[3];
    const float m = S * (1.0f / DIMM);
    const float var = Q * (1.0f / DIMM) - m*m;
    const float r = rsqrtf(var + 1e-5f);

    const float4 wv = *(const float4*)&w[tid*4];
    const float4 bv = *(const float4*)&b[tid*4];
    float4 o4;
    o4.x = (v.x - m) * r * wv.x + bv.x;
    o4.y = (v.y - m) * r * wv.y + bv.y;
    o4.z = (v.z - m) * r * wv.z + bv.z;
    o4.w = (v.w - m) * r * wv.w + bv.w;
    if (MODE == 0) {
        o4.x = tf32r_(o4.x); o4.y = tf32r_(o4.y);
        o4.z = tf32r_(o4.z); o4.w = tf32r_(o4.w);
        *(float4*)&a_xn[(size_t)row*DIMM + tid*4] = o4;
    } else {
        *(float4*)&out_arg[(size_t)row*DIMM + tid*4] = o4;
    }
}

// ---------------- cp.async tf32 mma GEMM: C[M,N] = A[M,K] * W[N,K]^T -------------
// Single-pass tf32. LDW=40 stride + LDS.64 fragment feed via k-permutation:
// logical mma k lanes (t4, t4+4) <-> global k (2*t4, 2*t4+1); A and B agree.
// MODE 0: in_proj  MODE 1: x_proj  MODE 2: out_proj  MODE 3: dt_proj
template<int BM, int BN, int STAGES, int MODE>
__global__ void __launch_bounds__(256, 2) mma_gemm(
    const float* __restrict__ Ea, const float* __restrict__ Eb, int K)
{
    constexpr int BK = 32;
    constexpr int LDW = 40;                 // floats per row in SMEM (bank-safe for 8B)
    constexpr int ABY = BM*LDW*4;           // bytes
    constexpr int WBY = BN*LDW*4;
    constexpr int STAGEB = ABY + WBY;
    constexpr int NWN = BN/32, NWM = 8/NWN;
    constexpr int WM = BM/NWM, WN = 32;
    constexpr int MI = WM/16, NI = WN/8;
    static_assert(NWN*NWM == 8 && MI >= 1 && NI >= 1, "warp tiling");
    static_assert((BM*8) % 256 == 0 && (BN*8) % 256 == 0, "cp.async coverage");

    extern __shared__ __align__(16) char dsm[];
    const uint32_t sbase = smem_u32_(dsm);
    const int tid = threadIdx.x;
    const int w = tid >> 5, lane = tid & 31;
    const int wm = w / NWN, wn = w % NWN;
    const int g = lane >> 2, t4 = lane & 3;
    const int bx = blockIdx.x, by = blockIdx.y, bz = blockIdx.z;

    const float *A, *W;
    if (MODE == 0)      { A = a_xn; W = w_in; }
    else if (MODE == 1) { A = a_uc + (size_t)bz*ROWS*DINN; W = w_xp + (size_t)bz*64*1024; }
    else if (MODE == 2) { A = a_yc; W = w_op; }
    else                { A = a_dt + (size_t)bz*ROWS*DTRR; W = w_dt + (size_t)bz*1024*32; }

    auto issue = [&](int buf, int k0) {
        const uint32_t st = sbase + buf*STAGEB;
#pragma unroll
        for (int u = 0; u < BM*8/256; ++u) {
            const int idx = tid + u*256;
            const int r = idx >> 3, ck = idx & 7;
            const size_t go = (size_t)(by*BM + r)*K + k0 + ck*4;
            CPA16(st + r*(LDW*4) + ck*16, gaddr_(A + go));
        }
#pragma unroll
        for (int u = 0; u < BN*8/256; ++u) {
            const int idx = tid + u*256;
            const int r = idx >> 3, ck = idx & 7;
            const size_t go = (size_t)(bx*BN + r)*K + k0 + ck*4;
            CPA16(st + ABY + r*(LDW*4) + ck*16, gaddr_(W + go));
        }
    };

    float c[MI][NI][4];
#pragma unroll
    for (int i = 0; i < MI; ++i)
#pragma unroll
        for (int j = 0; j < NI; ++j) {
            c[i][j][0] = 0.f; c[i][j][1] = 0.f; c[i][j][2] = 0.f; c[i][j][3] = 0.f;
        }

    auto compute = [&](int buf) {
        const float* sA = (const float*)(dsm + buf*STAGEB);
        const float* sW = (const float*)(dsm + buf*STAGEB + ABY);
#pragma unroll
        for (int kk = 0; kk < 4; ++kk) {        // 4 k8-steps per BK=32
            const int ko = kk*8 + 2*t4;
            uint32_t af[MI][4];
#pragma unroll
            for (int mi = 0; mi < MI; ++mi) {
                const int r = wm*WM + mi*16 + g;
                const float2 lo = *(const float2*)&sA[r*LDW + ko];
                const float2 hi = *(const float2*)&sA[(r+8)*LDW + ko];
                af[mi][0] = __float_as_uint(lo.x);
                af[mi][1] = __float_as_uint(hi.x);
                af[mi][2] = __float_as_uint(lo.y);
                af[mi][3] = __float_as_uint(hi.y);
            }
            uint32_t bf[NI][2];
#pragma unroll
            for (int ni = 0; ni < NI; ++ni) {
                const int n = wn*WN + ni*8 + g;
                const float2 bp = *(const float2*)&sW[n*LDW + ko];
                bf[ni][0] = __float_as_uint(bp.x);
                bf[ni][1] = __float_as_uint(bp.y);
            }
#pragma unroll
            for (int mi = 0; mi < MI; ++mi)
#pragma unroll
                for (int ni = 0; ni < NI; ++ni)
                    mma_tf32_(c[mi][ni], af[mi], bf[ni]);
        }
    };

    const int nch = K / BK;
#pragma unroll
    for (int s = 0; s < STAGES-1; ++s) {
        if (s < nch) issue(s, s*BK);
        CPCOMMIT();
    }
    for (int ch = 0; ch < nch; ++ch) {
        cpwait_<STAGES-2>();
        __syncthreads();
        const int nx = ch + STAGES - 1;
        if (nx < nch) issue(nx % STAGES, nx*BK);
        CPCOMMIT();
        compute(ch % STAGES);
    }

    // ---- epilogue ----
    const int r0 = by*BM + wm*WM + g;
    const int c0b = bx*BN + wn*WN + 2*t4;
#pragma unroll
    for (int mi = 0; mi < MI; ++mi)
#pragma unroll
        for (int ni = 0; ni < NI; ++ni) {
#pragma unroll
            for (int half = 0; half < 2; ++half) {
                const int row = r0 + mi*16 + half*8;
                const int col = c0b + ni*8;
                const float v0 = c[mi][ni][half*2+0];
                const float v1 = c[mi][ni][half*2+1];

                if (MODE == 0) {
                    if (col < DINN) {
                        *(float2*)&g_u[(size_t)row*DINN + col] = make_float2(v0, v1);
                    } else {
                        *(float2*)&g_g[(size_t)row*DINN + col - DINN] =
                            make_float2(siluf_(v0), siluf_(v1));
                    }
                } else if (MODE == 1) {
                    const size_t rb = (size_t)bz*ROWS + row;
                    if (col < DTRR) {
                        *(float2*)&a_dt[rb*DTRR + col] = make_float2(tf32r_(v0), tf32r_(v1));
                    } else if (col < DTRR+DSTT) {
                        g_bc[rb*(2*DSTT) + 2*(col - DTRR)]     = v0;
                        g_bc[rb*(2*DSTT) + 2*(col - DTRR) + 2] = v1;
                    } else {
                        g_bc[rb*(2*DSTT) + 2*(col - DTRR - DSTT) + 1] = v0;
                        g_bc[rb*(2*DSTT) + 2*(col - DTRR - DSTT) + 3] = v1;
                    }
                } else if (MODE == 2) {
                    const float2 e = *(const float2*)&Ea[(size_t)row*DIMM + col];
                    *(float2*)&g_out[(size_t)row*DIMM + col] = make_float2(v0 + e.x, v1 + e.y);
                } else { // MODE 3: delta only
                    const float* bias = bz ? Eb : Ea;
                    const float d0 = softplusf_(v0 + bias[col]);
                    const float d1 = softplusf_(v1 + bias[col+1]);
                    *(float2*)&g_dl[((size_t)bz*ROWS + row)*DINN + col] = make_float2(d0, d1);
                }
            }
        }
}

// ---------------- causal depthwise conv (K=4) + SiLU -> tf32-rounded fp32 --------
__global__ void __launch_bounds__(256) conv_kernel(
    const float* __restrict__ wf, const float* __restrict__ bf,
    const float* __restrict__ wb, const float* __restrict__ bw_)
{
    const int d  = blockIdx.x*256 + threadIdx.x;
    const int t0 = blockIdx.y*8;
    const int b  = blockIdx.z >> 1;
    const int br = blockIdx.z & 1;

    const float* wp = br ? wb : wf;
    const float w0 = wp[d*CK+0], w1 = wp[d*CK+1], w2 = wp[d*CK+2], w3 = wp[d*CK+3];
    const float bias = (br ? bw_ : bf)[d];

    float v[11];
#pragma unroll
    for (int j = 0; j < 11; ++j) {
        const int i = t0 - 3 + j;
        if (i < 0) { v[j] = 0.0f; }
        else {
            const int tt = br ? (LL-1-i) : i;
            v[j] = g_u[((size_t)b*LL + tt)*DINN + d];
        }
    }
    const size_t ob = ((size_t)br*ROWS + (size_t)b*LL + t0)*DINN + d;
#pragma unroll
    for (int m = 0; m < 8; ++m) {
        float a = fmaf(w3, v[m+3], fmaf(w2, v[m+2], fmaf(w1, v[m+1], fmaf(w0, v[m], bias))));
        a_uc[ob + (size_t)m*DINN] = tf32r_(siluf_(a));
    }
}

// ---------------- chunked selective scan ----------------
// pass 1: per-chunk local scan from h=0 -> (h_end, decay product) per state
__global__ void __launch_bounds__(128) scan_p1(
    const float* __restrict__ Alog_fw, const float* __restrict__ Alog_bw)
{
    const int tid = threadIdx.x;
    const int warp = tid >> 5, lane = tid & 31;
    const int c = lane >> 3, s = lane & 7;
    const int b  = blockIdx.y;
    const int br = blockIdx.z & 1;
    const int ck = blockIdx.z >> 1;
    const int d  = blockIdx.x*16 + warp*4 + c;

    const float* Alog = br ? Alog_bw : Alog_fw;
    const float a20 = -expf(Alog[d*DSTT + 2*s + 0]) * 1.44269504088896f;
    const float a21 = -expf(Alog[d*DSTT + 2*s + 1]) * 1.44269504088896f;

    const size_t i0 = ((size_t)br*ROWS + (size_t)b*LL + (size_t)ck*CL)*DINN + d;
    const float* dlP = g_dl + i0;
    const float* ucP = a_uc + i0;
    const float* bcP = g_bc + ((size_t)br*ROWS + (size_t)b*LL + (size_t)ck*CL)*(2*DSTT) + 4*s;

    float h0 = 0.f, h1 = 0.f, p0 = 1.f, p1 = 1.f;
#pragma unroll 4
    for (int t = 0; t < CL; ++t) {
        const float dv = *dlP;
        const float uv = *ucP;
        const float4 bc = *(const float4*)bcP;
        const float e0 = ex2f_(dv * a20);
        const float e1 = ex2f_(dv * a21);
        const float duu = dv * uv;
        h0 = fmaf(e0, h0, duu * bc.x);
        h1 = fmaf(e1, h1, duu * bc.z);
        p0 *= e0; p1 *= e1;
        dlP += DINN; ucP += DINN; bcP += 2*DSTT;
    }
    g_ch[((((size_t)br*BB + b)*NC + ck)*DINN + d)*8 + s] = make_float4(h0, p0, h1, p1);
}

// pass 2: sequential combine over chunks -> incoming state per chunk
__global__ void __launch_bounds__(256) scan_p2()
{
    const int idx = blockIdx.x*256 + threadIdx.x;   // 2*BB*DINN*8 = 32768
    const int s = idx & 7;
    const int d = (idx >> 3) & (DINN-1);
    const int b = (idx >> 13) & (BB-1);
    const int br = idx >> 14;
    const size_t base = (((size_t)br*BB + b)*NC)*DINN*8 + (size_t)d*8 + s;

    float h0 = 0.f, h1 = 0.f;
#pragma unroll
    for (int ck = 0; ck < NC; ++ck) {
        const size_t o = base + (size_t)ck*DINN*8;
        const float4 cp = g_ch[o];
        g_hin[o] = make_float2(h0, h1);
        h0 = fmaf(cp.y, h0, cp.x);
        h1 = fmaf(cp.w, h1, cp.z);
    }
}

// pass 3: local scan seeded with incoming state; emit.
// BR=0 (fw): write y_f to a_yc (fp32, global time = branch time).
// BR=1 (bw): a_yc[rev t] = tf32((y_f + y_b) * g)  -- runs AFTER the fw launch.
template<int BR>
__global__ void __launch_bounds__(128) scan_p3(
    const float* __restrict__ Alog, const float* __restrict__ Dv)
{
    const int tid = threadIdx.x;
    const int warp = tid >> 5, lane = tid & 31;
    const int c = lane >> 3, s = lane & 7;
    const int b  = blockIdx.y;
    const int ck = blockIdx.z;
    const int d  = blockIdx.x*16 + warp*4 + c;

    const float a20 = -expf(Alog[d*DSTT + 2*s + 0]) * 1.44269504088896f;
    const float a21 = -expf(Alog[d*DSTT + 2*s + 1]) * 1.44269504088896f;
    const float Dd  = Dv[d];

    const size_t i0 = ((size_t)BR*ROWS + (size_t)b*LL + (size_t)ck*CL)*DINN + d;
    const float* dlP = g_dl + i0;
    const float* ucP = a_uc + i0;
    const float* bcP = g_bc + ((size_t)BR*ROWS + (size_t)b*LL + (size_t)ck*CL)*(2*DSTT) + 4*s;

    // output pointer: fw walks forward from global t = ck*CL; bw walks backward from LL-1-ck*CL
    float* yP;
    if (BR == 0) yP = a_yc + ((size_t)b*LL + (size_t)ck*CL)*DINN + d;
    else         yP = a_yc + ((size_t)b*LL + (LL-1 - (size_t)ck*CL))*DINN + d;
    const float* gP = (BR == 1) ? (g_g + ((size_t)b*LL + (LL-1 - (size_t)ck*CL))*DINN + d) : nullptr;

    const float2 hin = g_hin[((((size_t)BR*BB + b)*NC + ck)*DINN + d)*8 + s];
    float h0 = hin.x, h1 = hin.y;
#pragma unroll 4
    for (int t = 0; t < CL; ++t) {
        const float dv = *dlP;
        const float uv = *ucP;
        const float4 bc = *(const float4*)bcP;
        const float e0 = ex2f_(dv * a20);
        const float e1 = ex2f_(dv * a21);
        const float duu = dv * uv;
        h0 = fmaf(e0, h0, duu * bc.x);
        h1 = fmaf(e1, h1, duu * bc.z);
        float p = fmaf(h1, bc.w, h0 * bc.y);
        p += __shfl_xor_sync(0xffffffffu, p, 1);
        p += __shfl_xor_sync(0xffffffffu, p, 2);
        p += __shfl_xor_sync(0xffffffffu, p, 4);
        if (s == 0) {
            const float yv = fmaf(Dd, uv, p);
            if (BR == 0) {
                *yP = yv;
            } else {
                *yP = tf32r_((*yP + yv) * (*gP));
            }
        }
        dlP += DINN; ucP += DINN; bcP += 2*DSTT;
        if (BR == 0) { yP += DINN; }
        else         { yP -= DINN; gP -= DINN; }
    }
}

// ---------------- launch ----------------
extern "C" void kernel_launch(void* const* d_in, const int* in_sizes, int n_in,
                              void* d_out, int out_size)
{
    const float* x         = (const float*)d_in[0];
    const float* ln1_w     = (const float*)d_in[1];
    const float* ln1_b     = (const float*)d_in[2];
    const float* ln2_w     = (const float*)d_in[3];
    const float* ln2_b     = (const float*)d_in[4];
    const float* in_proj_w = (const float*)d_in[5];
    const float* conv_w_fw = (const float*)d_in[6];
    const float* conv_b_fw = (const float*)d_in[7];
    const float* xproj_fw  = (const float*)d_in[8];
    const float* dt_w_fw   = (const float*)d_in[9];
    const float* dt_b_fw   = (const float*)d_in[10];
    const float* Alog_fw   = (const float*)d_in[11];
    const float* D_fw      = (const float*)d_in[12];
    const float* conv_w_bw = (const float*)d_in[13];
    const float* conv_b_bw = (const float*)d_in[14];
    const float* xproj_bw  = (const float*)d_in[15];
    const float* dt_w_bw   = (const float*)d_in[16];
    const float* dt_b_bw   = (const float*)d_in[17];
    const float* Alog_bw   = (const float*)d_in[18];
    const float* D_bw      = (const float*)d_in[19];
    const float* out_proj_w= (const float*)d_in[20];
    float* out             = (float*)d_out;

    // stage bytes = (BM + BN)*LDW*4 = (BM+BN)*160
    const int SM_IN = 3 * (128*160 + 64*160);   // 92160 (in/out proj)
    const int SM_XP = 3 * (64*160  + 64*160);   // 61440 (x_proj, BM=64)
    const int SM_DT = 2 * (128*160 + 64*160);   // 61440 (dt_proj)
    cudaFuncSetAttribute(mma_gemm<128,64,3,0>, cudaFuncAttributeMaxDynamicSharedMemorySize, SM_IN);
    cudaFuncSetAttribute(mma_gemm<64, 64,3,1>, cudaFuncAttributeMaxDynamicSharedMemorySize, SM_XP);
    cudaFuncSetAttribute(mma_gemm<128,64,3,2>, cudaFuncAttributeMaxDynamicSharedMemorySize, SM_IN);
    cudaFuncSetAttribute(mma_gemm<128,64,2,3>, cudaFuncAttributeMaxDynamicSharedMemorySize, SM_DT);

    // 0) tf32-round all weights
    wconv_kernel<<<TSEG5/256, 256>>>(in_proj_w, out_proj_w, xproj_fw, xproj_bw, dt_w_fw, dt_w_bw);

    // 1) LN1: x -> a_xn (tf32-rounded)
    ln_kernel<0><<<ROWS, 128>>>(x, ln1_w, ln1_b, nullptr);

    // 2) in_proj: (4096,512) @ (2048,512)^T -> g_u / g_g
    mma_gemm<128,64,3,0><<<dim3(2048/64, ROWS/128, 1), 256, SM_IN>>>(nullptr, nullptr, DIMM);

    // 3) causal conv + SiLU -> a_uc (tf32-rounded)
    conv_kernel<<<dim3(DINN/256, LL/8, BB*2), 256>>>(conv_w_fw, conv_b_fw, conv_w_bw, conv_b_bw);

    // 4) x_proj both branches -> a_dt (tf32-rounded) + g_bc
    mma_gemm<64,64,3,1><<<dim3(1, ROWS/64, 2), 256, SM_XP>>>(nullptr, nullptr, DINN);

    // 5) dt_proj both branches: softplus(+bias) -> g_dl (delta only)
    mma_gemm<128,64,2,3><<<dim3(DINN/64, ROWS/128, 2), 256, SM_DT>>>(dt_b_fw, dt_b_bw, DTRR);

    // 6) chunked selective scan (p3 fused with gating/combine)
    scan_p1<<<dim3(DINN/16, BB, 2*NC), 128>>>(Alog_fw, Alog_bw);
    scan_p2<<<(2*BB*DINN*8)/256, 256>>>();
    scan_p3<0><<<dim3(DINN/16, BB, NC), 128>>>(Alog_fw, D_fw);
    scan_p3<1><<<dim3(DINN/16, BB, NC), 128>>>(Alog_bw, D_bw);

    // 7) out_proj + residual -> g_out
    mma_gemm<128,64,3,2><<<dim3(DIMM/64, ROWS/128, 1), 256, SM_IN>>>(x, nullptr, DINN);

    // 8) LN2
    ln_kernel<1><<<ROWS, 128>>>(nullptr, ln2_w, ln2_b, out);
}